// round 15
// baseline (speedup 1.0000x reference)
#include <cuda_runtime.h>
#include <cuda_bf16.h>
#include <cfloat>
#include <math.h>
#include <cstdint>

#define S 2048
#define HID 4096
#define NH 32
#define D 128
#define QKV3 12288
#define ROT 32
#define HALF 16
#define HEAVY 204
#define RECENT 204
#define SEL (S - RECENT)       /* 1844 */
#define MASKW (S + 1)          /* 2049 */

#define BM 128
#define BN 128
#define BK 8
#define TM 8
#define TN 8
#define GBK 16
#define KP 132                 /* padded smem row stride for tf32 planes */

typedef unsigned long long ull;

// ------------------------- scratch (static device globals; no allocs) ------
__device__ float g_q[(size_t)NH * S * D];
__device__ float g_k[(size_t)NH * S * D];
__device__ float g_v[(size_t)NH * S * D];
__device__ float g_w[(size_t)NH * S * S];            // 536 MB
__device__ float g_ot[(size_t)S * HID];
__device__ float g_colsum[NH * S];

// ------------------------- packed f32x2 helpers ----------------------------
__device__ __forceinline__ ull pack_dup(float a) {
    ull d; asm("mov.b64 %0, {%1, %2};" : "=l"(d) : "f"(a), "f"(a)); return d;
}
__device__ __forceinline__ void ffma2(ull& c, ull a, ull b) {
    asm("fma.rn.f32x2 %0, %1, %2, %0;" : "+l"(c) : "l"(a), "l"(b));
}
__device__ __forceinline__ void unpack2(ull v, float& lo, float& hi) {
    asm("mov.b64 {%0, %1}, %2;" : "=f"(lo), "=f"(hi) : "l"(v));
}

// ------------------------- tf32 helpers ------------------------------------
__device__ __forceinline__ float to_tf32(float x) {
    float y;
    asm("cvt.rna.tf32.f32 %0, %1;" : "=f"(y) : "f"(x));
    return y;
}
__device__ __forceinline__ void mma_tf32(float c[4], const unsigned a[4], const unsigned b[2]) {
    asm volatile(
        "mma.sync.aligned.m16n8k8.row.col.f32.tf32.tf32.f32 "
        "{%0,%1,%2,%3}, {%4,%5,%6,%7}, {%8,%9}, {%0,%1,%2,%3};"
        : "+f"(c[0]), "+f"(c[1]), "+f"(c[2]), "+f"(c[3])
        : "r"(a[0]), "r"(a[1]), "r"(a[2]), "r"(a[3]), "r"(b[0]), "r"(b[1]));
}

// ===== FUSED QKV: grid (96, 16).  x<64 -> QK tile (FFMA2, exact fp32);
// x>=64 -> V tile (single-tf32 MMA, output-0 path).  One smem union so the
// two CTA flavors co-reside per SM and drive different pipes concurrently.
// Per-thread math of each path identical to round 13/14 -> bit-identical.
#define SMEM_BYTES 33792   /* max(QK 32768, tf32 2*16896) */

__global__ void __launch_bounds__(256, 2)
fused_qkv(const float* __restrict__ A,
          const float* __restrict__ B,
          const float* __restrict__ bias,
          float* __restrict__ q, float* __restrict__ k,
          float* __restrict__ v, int K) {
    __shared__ __align__(16) char smem_raw[SMEM_BYTES];
    const int t = threadIdx.x;
    const int by = blockIdx.y * 128;

    if (blockIdx.x < 64) {
        // ---------------- QK path: exact fp32 FFMA2 ----------------
        float (*As)[GBK][128] = reinterpret_cast<float (*)[GBK][128]>(smem_raw);
        float (*Bs)[GBK][128] = reinterpret_cast<float (*)[GBK][128]>(smem_raw + 16384);
        const int wtile = (blockIdx.x >> 1) * 3 + (blockIdx.x & 1);
        const int bx = wtile * 128;
        const int tr = t >> 4, tc = t & 15;
        const int lr = t & 127;
        const int lc = (t >> 7) * 8;

        const float* Ap = A + (size_t)(by + lr) * K + lc;
        const float* Bp = B + (size_t)(bx + lr) * K + lc;

        float4 a0, a1, b0, b1;
        a0 = *(const float4*)(Ap);     a1 = *(const float4*)(Ap + 4);
        b0 = *(const float4*)(Bp);     b1 = *(const float4*)(Bp + 4);

        ull acc2[TM][TN / 2];
#pragma unroll
        for (int i = 0; i < TM; ++i)
#pragma unroll
            for (int j = 0; j < TN / 2; ++j) acc2[i][j] = 0ULL;

        const int nk = K / GBK;
#pragma unroll 1
        for (int i = 0; i < nk; ++i) {
            const int cur = i & 1;
            As[cur][lc + 0][lr] = a0.x; As[cur][lc + 1][lr] = a0.y;
            As[cur][lc + 2][lr] = a0.z; As[cur][lc + 3][lr] = a0.w;
            As[cur][lc + 4][lr] = a1.x; As[cur][lc + 5][lr] = a1.y;
            As[cur][lc + 6][lr] = a1.z; As[cur][lc + 7][lr] = a1.w;
            Bs[cur][lc + 0][lr] = b0.x; Bs[cur][lc + 1][lr] = b0.y;
            Bs[cur][lc + 2][lr] = b0.z; Bs[cur][lc + 3][lr] = b0.w;
            Bs[cur][lc + 4][lr] = b1.x; Bs[cur][lc + 5][lr] = b1.y;
            Bs[cur][lc + 6][lr] = b1.z; Bs[cur][lc + 7][lr] = b1.w;
            __syncthreads();
            if (i + 1 < nk) {
                const float* An = Ap + (size_t)(i + 1) * GBK;
                const float* Bn = Bp + (size_t)(i + 1) * GBK;
                a0 = *(const float4*)(An);     a1 = *(const float4*)(An + 4);
                b0 = *(const float4*)(Bn);     b1 = *(const float4*)(Bn + 4);
            }
#pragma unroll
            for (int kk = 0; kk < GBK; ++kk) {
                float a[TM];
                *(float4*)&a[0] = *(const float4*)&As[cur][kk][tr * TM];
                *(float4*)&a[4] = *(const float4*)&As[cur][kk][tr * TM + 4];
                ulonglong2 q0 = *(const ulonglong2*)&Bs[cur][kk][tc * TN];
                ulonglong2 q1 = *(const ulonglong2*)&Bs[cur][kk][tc * TN + 4];
                ull b2[4] = { q0.x, q0.y, q1.x, q1.y };
                ull pa[TM];
#pragma unroll
                for (int x = 0; x < TM; ++x) pa[x] = pack_dup(a[x]);
#pragma unroll
                for (int x = 0; x < TM; ++x)
#pragma unroll
                    for (int y = 0; y < TN / 2; ++y) ffma2(acc2[x][y], pa[x], b2[y]);
            }
            __syncthreads();
        }

        const int typ = wtile % 3;           // 0 = Q, 1 = K
        const int h = wtile / 3;
        float* outp = (typ == 0) ? q : k;
        const int cb = tc * TN;
        float bsv[TN];
#pragma unroll
        for (int j = 0; j < TN; ++j) bsv[j] = bias[bx + cb + j];
#pragma unroll
        for (int i = 0; i < TM; ++i) {
            float c[TN];
#pragma unroll
            for (int j = 0; j < TN / 2; ++j) unpack2(acc2[i][j], c[2 * j], c[2 * j + 1]);
            const int row = by + tr * TM + i;
            const size_t o = ((size_t)h * S + row) * D + cb;
            float4 v0, v1;
            v0.x = c[0] + bsv[0]; v0.y = c[1] + bsv[1];
            v0.z = c[2] + bsv[2]; v0.w = c[3] + bsv[3];
            v1.x = c[4] + bsv[4]; v1.y = c[5] + bsv[5];
            v1.z = c[6] + bsv[6]; v1.w = c[7] + bsv[7];
            *(float4*)&outp[o]     = v0;
            *(float4*)&outp[o + 4] = v1;
        }
    } else {
        // ---------------- V path: single-tf32 MMA (double-buffered) --------
        float (*Ah)[16][KP] = reinterpret_cast<float (*)[16][KP]>(smem_raw);
        float (*Bh)[16][KP] = reinterpret_cast<float (*)[16][KP]>(smem_raw + 16896);
        const int h = blockIdx.x - 64;       // head
        const int bx = (h * 3 + 2) * 128;
        const int lane = t & 31;
        const int warp = t >> 5;
        const int wr = (warp >> 2) * 64;
        const int wc = (warp & 3) * 32;
        const int g = lane >> 2;
        const int kq = lane & 3;
        const int lr = t & 127;
        const int lc = (t >> 7) * 8;

        const float* Ap = A + (size_t)(by + lr) * K + lc;
        const float* Bp = B + (size_t)(bx + lr) * K + lc;

        float4 a0, a1, b0, b1;
        a0 = *(const float4*)(Ap);     a1 = *(const float4*)(Ap + 4);
        b0 = *(const float4*)(Bp);     b1 = *(const float4*)(Bp + 4);

        {
            float a8[8], b8[8];
            *(float4*)&a8[0] = a0; *(float4*)&a8[4] = a1;
            *(float4*)&b8[0] = b0; *(float4*)&b8[4] = b1;
#pragma unroll
            for (int j = 0; j < 8; ++j) {
                Ah[0][lc + j][lr] = to_tf32(a8[j]);
                Bh[0][lc + j][lr] = to_tf32(b8[j]);
            }
        }
        __syncthreads();

        float acc[4][4][4] = {};
        const int nk = K / 16;

#pragma unroll 1
        for (int i = 0; i < nk; ++i) {
            const int cur = i & 1;
            if (i + 1 < nk) {
                const float* An = Ap + (size_t)(i + 1) * 16;
                const float* Bn = Bp + (size_t)(i + 1) * 16;
                a0 = *(const float4*)(An);     a1 = *(const float4*)(An + 4);
                b0 = *(const float4*)(Bn);     b1 = *(const float4*)(Bn + 4);
            }
#pragma unroll
            for (int ks = 0; ks < 2; ++ks) {
                const int kb = ks * 8;
                unsigned bf[4][2];
#pragma unroll
                for (int nt = 0; nt < 4; ++nt) {
                    const int cn = wc + nt * 8 + g;
                    bf[nt][0] = __float_as_uint(Bh[cur][kb + kq][cn]);
                    bf[nt][1] = __float_as_uint(Bh[cur][kb + kq + 4][cn]);
                }
#pragma unroll
                for (int mt = 0; mt < 4; ++mt) {
                    const int r = wr + mt * 16 + g;
                    unsigned af[4];
                    af[0] = __float_as_uint(Ah[cur][kb + kq][r]);
                    af[1] = __float_as_uint(Ah[cur][kb + kq][r + 8]);
                    af[2] = __float_as_uint(Ah[cur][kb + kq + 4][r]);
                    af[3] = __float_as_uint(Ah[cur][kb + kq + 4][r + 8]);
#pragma unroll
                    for (int nt = 0; nt < 4; ++nt)
                        mma_tf32(acc[mt][nt], af, bf[nt]);
                }
            }
            if (i + 1 < nk) {
                const int nxt = cur ^ 1;
                float a8[8], b8[8];
                *(float4*)&a8[0] = a0; *(float4*)&a8[4] = a1;
                *(float4*)&b8[0] = b0; *(float4*)&b8[4] = b1;
#pragma unroll
                for (int j = 0; j < 8; ++j) {
                    Ah[nxt][lc + j][lr] = to_tf32(a8[j]);
                    Bh[nxt][lc + j][lr] = to_tf32(b8[j]);
                }
            }
            __syncthreads();
        }

#pragma unroll
        for (int mt = 0; mt < 4; ++mt) {
            const int r = by + wr + mt * 16 + g;
#pragma unroll
            for (int nt = 0; nt < 4; ++nt) {
                const int cn = wc + nt * 8 + kq * 2;
                const float s0 = bias[bx + cn];
                const float s1 = bias[bx + cn + 1];
                const size_t o0 = ((size_t)h * S + r) * D + cn;
                const size_t o1 = ((size_t)h * S + r + 8) * D + cn;
                v[o0]     = acc[mt][nt][0] + s0;
                v[o0 + 1] = acc[mt][nt][1] + s1;
                v[o1]     = acc[mt][nt][2] + s0;
                v[o1 + 1] = acc[mt][nt][3] + s1;
            }
        }
    }
}

// ===== FUSED dense + colsum: grid (32, 18).  y<16 -> dense tf32 tile;
// y>=16 -> colsum blocks (exact causal: sum q from k).
__global__ void __launch_bounds__(256)
fused_dense_colsum(const float* __restrict__ A,
                   const float* __restrict__ B,
                   const float* __restrict__ bias,
                   float* __restrict__ out) {
    __shared__ __align__(16) char smem_raw[SMEM_BYTES];
    const int t = threadIdx.x;

    if (blockIdx.y >= 16) {
        // ---------------- colsum path ----------------
        const int bid = (blockIdx.y - 16) * 32 + blockIdx.x;   // 0..63
        const int h = bid >> 1;
        const int base = (bid & 1) * 1024;
        const float* wb = g_w + (size_t)h * S * S;
#pragma unroll 1
        for (int it = 0; it < 4; ++it) {
            const int kcol = base + it * 256 + t;
            float s = 0.f;
#pragma unroll 4
            for (int qq = kcol; qq < S; ++qq) s += wb[(size_t)qq * S + kcol];
            g_colsum[h * S + kcol] = s;
        }
        return;
    }

    // ---------------- dense tf32 tile ----------------
    float (*Ah)[16][KP] = reinterpret_cast<float (*)[16][KP]>(smem_raw);
    float (*Bh)[16][KP] = reinterpret_cast<float (*)[16][KP]>(smem_raw + 16896);
    const int bx = blockIdx.x * 128;
    const int by = blockIdx.y * 128;
    const int K = HID;
    const int lane = t & 31;
    const int warp = t >> 5;
    const int wr = (warp >> 2) * 64;
    const int wc = (warp & 3) * 32;
    const int g = lane >> 2;
    const int kq = lane & 3;
    const int lr = t & 127;
    const int lc = (t >> 7) * 8;

    const float* Ap = A + (size_t)(by + lr) * K + lc;
    const float* Bp = B + (size_t)(bx + lr) * K + lc;

    float4 a0, a1, b0, b1;
    a0 = *(const float4*)(Ap);     a1 = *(const float4*)(Ap + 4);
    b0 = *(const float4*)(Bp);     b1 = *(const float4*)(Bp + 4);

    {
        float a8[8], b8[8];
        *(float4*)&a8[0] = a0; *(float4*)&a8[4] = a1;
        *(float4*)&b8[0] = b0; *(float4*)&b8[4] = b1;
#pragma unroll
        for (int j = 0; j < 8; ++j) {
            Ah[0][lc + j][lr] = to_tf32(a8[j]);
            Bh[0][lc + j][lr] = to_tf32(b8[j]);
        }
    }
    __syncthreads();

    float acc[4][4][4] = {};
    const int nk = K / 16;

#pragma unroll 1
    for (int i = 0; i < nk; ++i) {
        const int cur = i & 1;
        if (i + 1 < nk) {
            const float* An = Ap + (size_t)(i + 1) * 16;
            const float* Bn = Bp + (size_t)(i + 1) * 16;
            a0 = *(const float4*)(An);     a1 = *(const float4*)(An + 4);
            b0 = *(const float4*)(Bn);     b1 = *(const float4*)(Bn + 4);
        }
#pragma unroll
        for (int ks = 0; ks < 2; ++ks) {
            const int kb = ks * 8;
            unsigned bf[4][2];
#pragma unroll
            for (int nt = 0; nt < 4; ++nt) {
                const int cn = wc + nt * 8 + g;
                bf[nt][0] = __float_as_uint(Bh[cur][kb + kq][cn]);
                bf[nt][1] = __float_as_uint(Bh[cur][kb + kq + 4][cn]);
            }
#pragma unroll
            for (int mt = 0; mt < 4; ++mt) {
                const int r = wr + mt * 16 + g;
                unsigned af[4];
                af[0] = __float_as_uint(Ah[cur][kb + kq][r]);
                af[1] = __float_as_uint(Ah[cur][kb + kq][r + 8]);
                af[2] = __float_as_uint(Ah[cur][kb + kq + 4][r]);
                af[3] = __float_as_uint(Ah[cur][kb + kq + 4][r + 8]);
#pragma unroll
                for (int nt = 0; nt < 4; ++nt)
                    mma_tf32(acc[mt][nt], af, bf[nt]);
            }
        }
        if (i + 1 < nk) {
            const int nxt = cur ^ 1;
            float a8[8], b8[8];
            *(float4*)&a8[0] = a0; *(float4*)&a8[4] = a1;
            *(float4*)&b8[0] = b0; *(float4*)&b8[4] = b1;
#pragma unroll
            for (int j = 0; j < 8; ++j) {
                Ah[nxt][lc + j][lr] = to_tf32(a8[j]);
                Bh[nxt][lc + j][lr] = to_tf32(b8[j]);
            }
        }
        __syncthreads();
    }

#pragma unroll
    for (int mt = 0; mt < 4; ++mt) {
        const int r = by + wr + mt * 16 + g;
#pragma unroll
        for (int nt = 0; nt < 4; ++nt) {
            const int cn = wc + nt * 8 + kq * 2;
            const float s0 = bias[bx + cn];
            const float s1 = bias[bx + cn + 1];
            out[(size_t)r * HID + bx + cn]           = acc[mt][nt][0] + s0;
            out[(size_t)r * HID + bx + cn + 1]       = acc[mt][nt][1] + s1;
            out[(size_t)(r + 8) * HID + bx + cn]     = acc[mt][nt][2] + s0;
            out[(size_t)(r + 8) * HID + bx + cn + 1] = acc[mt][nt][3] + s1;
        }
    }
}

// ------------------------- in-place RoPE on q/k rotary dims ----------------
__global__ void rope_inplace(const int* __restrict__ pos) {
    int idx = blockIdx.x * 256 + threadIdx.x;
    if (idx >= NH * S * HALF) return;
    const int i = idx & (HALF - 1);
    const int s = (idx >> 4) & (S - 1);
    const int h = idx >> 15;
    const float tpos = (float)pos[s];
    const float inv = powf(10000.0f, -(float)i * (1.0f / 16.0f));
    const float f = tpos * inv;
    const float c = cosf(f), sn = sinf(f);
    const size_t o = ((size_t)h * S + s) * D;

    float q1 = g_q[o + i], q2 = g_q[o + i + HALF];
    g_q[o + i]        = q1 * c + (-q2) * sn;
    g_q[o + i + HALF] = q2 * c + q1 * sn;

    float k1 = g_k[o + i], k2 = g_k[o + i + HALF];
    g_k[o + i]        = k1 * c + (-k2) * sn;
    g_k[o + i + HALF] = k2 * c + k1 * sn;
}

// ------ scores = QK^T / sqrt(D), causal (FFMA2, double-buffered) -----------
__global__ void scores_kernel(const float* __restrict__ amask) {
    const int h = blockIdx.z;
    const int bq = blockIdx.y * BM;
    const int bk = blockIdx.x * BN;
    if (bk > bq + BM - 1) return;
    const float* A = g_q + (size_t)h * S * D;
    const float* B = g_k + (size_t)h * S * D;
    float* C = g_w + (size_t)h * S * S;

    __shared__ __align__(16) float As[2][BK][BM];
    __shared__ __align__(16) float Bs[2][BK][BN];
    const int t = threadIdx.x;
    const int tr = t >> 4, tc = t & 15;
    const int lrow = t >> 1, lseg = (t & 1) * 4;
    ull acc2[TM][TN / 2];
#pragma unroll
    for (int i = 0; i < TM; ++i)
#pragma unroll
        for (int j = 0; j < TN / 2; ++j) acc2[i][j] = 0ULL;
    const float* Ab = A + (size_t)(bq + lrow) * D + lseg;
    const float* Bb = B + (size_t)(bk + lrow) * D + lseg;

    {
        float4 av = *(const float4*)(Ab);
        float4 bv = *(const float4*)(Bb);
        As[0][lseg + 0][lrow] = av.x; As[0][lseg + 1][lrow] = av.y;
        As[0][lseg + 2][lrow] = av.z; As[0][lseg + 3][lrow] = av.w;
        Bs[0][lseg + 0][lrow] = bv.x; Bs[0][lseg + 1][lrow] = bv.y;
        Bs[0][lseg + 2][lrow] = bv.z; Bs[0][lseg + 3][lrow] = bv.w;
    }
    __syncthreads();

    const int nit = D / BK;
#pragma unroll 1
    for (int it = 0; it < nit; ++it) {
        const int cur = it & 1;
        float4 av, bv;
        if (it + 1 < nit) {
            av = *(const float4*)(Ab + (it + 1) * BK);
            bv = *(const float4*)(Bb + (it + 1) * BK);
        }
#pragma unroll
        for (int kk = 0; kk < BK; ++kk) {
            float a[TM];
            *(float4*)&a[0] = *(const float4*)&As[cur][kk][tr * TM];
            *(float4*)&a[4] = *(const float4*)&As[cur][kk][tr * TM + 4];
            ulonglong2 q0 = *(const ulonglong2*)&Bs[cur][kk][tc * TN];
            ulonglong2 q1 = *(const ulonglong2*)&Bs[cur][kk][tc * TN + 4];
            ull b2[4] = { q0.x, q0.y, q1.x, q1.y };
            ull pa[TM];
#pragma unroll
            for (int x = 0; x < TM; ++x) pa[x] = pack_dup(a[x]);
#pragma unroll
            for (int x = 0; x < TM; ++x)
#pragma unroll
                for (int y = 0; y < TN / 2; ++y) ffma2(acc2[x][y], pa[x], b2[y]);
        }
        if (it + 1 < nit) {
            const int nxt = cur ^ 1;
            As[nxt][lseg + 0][lrow] = av.x; As[nxt][lseg + 1][lrow] = av.y;
            As[nxt][lseg + 2][lrow] = av.z; As[nxt][lseg + 3][lrow] = av.w;
            Bs[nxt][lseg + 0][lrow] = bv.x; Bs[nxt][lseg + 1][lrow] = bv.y;
            Bs[nxt][lseg + 2][lrow] = bv.z; Bs[nxt][lseg + 3][lrow] = bv.w;
        }
        __syncthreads();
    }
    const float scale = 0.08838834764831845f;
#pragma unroll
    for (int i = 0; i < TM; ++i) {
        float c[TN];
#pragma unroll
        for (int j = 0; j < TN / 2; ++j) unpack2(acc2[i][j], c[2 * j], c[2 * j + 1]);
        const int q = bq + tr * TM + i;
#pragma unroll
        for (int j = 0; j < TN; ++j) {
            const int k = bk + tc * TN + j;
            if (k <= q) C[(size_t)q * S + k] = c[j] * scale + amask[k];
        }
    }
}

// ------------- row softmax (zero-fills only within diagonal block) ---------
__global__ void softmax_kernel() {
    const int q = blockIdx.x, h = blockIdx.y;
    float* row = g_w + (size_t)h * S * S + (size_t)q * S;
    __shared__ float buf[S];
    __shared__ float red[256];
    const int t = threadIdx.x;
    const int n = q + 1;
    const int edge = ((q >> 7) + 1) << 7;   // end of q's 128-diagonal block

    float m = -FLT_MAX;
    for (int i = t; i < n; i += 256) { float v = row[i]; buf[i] = v; m = fmaxf(m, v); }
    red[t] = m; __syncthreads();
    for (int off = 128; off; off >>= 1) {
        if (t < off) red[t] = fmaxf(red[t], red[t + off]);
        __syncthreads();
    }
    m = red[0]; __syncthreads();

    float sum = 0.f;
    for (int i = t; i < n; i += 256) { float e = expf(buf[i] - m); buf[i] = e; sum += e; }
    red[t] = sum; __syncthreads();
    for (int off = 128; off; off >>= 1) {
        if (t < off) red[t] += red[t + off];
        __syncthreads();
    }
    const float inv = 1.0f / red[0];

    for (int i = t; i < n; i += 256) row[i] = buf[i] * inv;
    for (int i = n + t; i < edge; i += 256) row[i] = 0.f;   // pv-visible zeros only
}

// ------ O = W @ V (causal-bounded K loop, FFMA2, double-buffered) ----------
__global__ void pv_kernel() {
    const int h = blockIdx.z;
    const int bq = blockIdx.y * BM;
    const float* A = g_w + (size_t)h * S * S;
    const float* B = g_v + (size_t)h * S * D;

    __shared__ __align__(16) float As[2][BK][BM];
    __shared__ __align__(16) float Bs[2][BK][BN];
    const int t = threadIdx.x;
    const int tr = t >> 4, tc = t & 15;
    const int lrow = t >> 1, lseg = (t & 1) * 4;
    ull acc2[TM][TN / 2];
#pragma unroll
    for (int i = 0; i < TM; ++i)
#pragma unroll
        for (int j = 0; j < TN / 2; ++j) acc2[i][j] = 0ULL;
    const int kmax = bq + BM;
    const int nit = kmax / BK;

    {
        float4 av = *(const float4*)(A + (size_t)(bq + lrow) * S + lseg);
        float4 bv = *(const float4*)(B + (size_t)(t >> 5) * D + (t & 31) * 4);
        As[0][lseg + 0][lrow] = av.x; As[0][lseg + 1][lrow] = av.y;
        As[0][lseg + 2][lrow] = av.z; As[0][lseg + 3][lrow] = av.w;
        *(float4*)&Bs[0][t >> 5][(t & 31) * 4] = bv;
    }
    __syncthreads();

#pragma unroll 1
    for (int it = 0; it < nit; ++it) {
        const int cur = it & 1;
        float4 av, bv;
        if (it + 1 < nit) {
            const int k0 = (it + 1) * BK;
            av = *(const float4*)(A + (size_t)(bq + lrow) * S + k0 + lseg);
            bv = *(const float4*)(B + (size_t)(k0 + (t >> 5)) * D + (t & 31) * 4);
        }
#pragma unroll
        for (int kk = 0; kk < BK; ++kk) {
            float a[TM];
            *(float4*)&a[0] = *(const float4*)&As[cur][kk][tr * TM];
            *(float4*)&a[4] = *(const float4*)&As[cur][kk][tr * TM + 4];
            ulonglong2 q0 = *(const ulonglong2*)&Bs[cur][kk][tc * TN];
            ulonglong2 q1 = *(const ulonglong2*)&Bs[cur][kk][tc * TN + 4];
            ull b2[4] = { q0.x, q0.y, q1.x, q1.y };
            ull pa[TM];
#pragma unroll
            for (int x = 0; x < TM; ++x) pa[x] = pack_dup(a[x]);
#pragma unroll
            for (int x = 0; x < TM; ++x)
#pragma unroll
                for (int y = 0; y < TN / 2; ++y) ffma2(acc2[x][y], pa[x], b2[y]);
        }
        if (it + 1 < nit) {
            const int nxt = cur ^ 1;
            As[nxt][lseg + 0][lrow] = av.x; As[nxt][lseg + 1][lrow] = av.y;
            As[nxt][lseg + 2][lrow] = av.z; As[nxt][lseg + 3][lrow] = av.w;
            *(float4*)&Bs[nxt][t >> 5][(t & 31) * 4] = bv;
        }
        __syncthreads();
    }
#pragma unroll
    for (int i = 0; i < TM; ++i) {
        float c[TN];
#pragma unroll
        for (int j = 0; j < TN / 2; ++j) unpack2(acc2[i][j], c[2 * j], c[2 * j + 1]);
        const size_t row = bq + tr * TM + i;
        *(float4*)&g_ot[row * HID + h * D + tc * TN]     = *(float4*)&c[0];
        *(float4*)&g_ot[row * HID + h * D + tc * TN + 4] = *(float4*)&c[4];
    }
}

// ------------------------- top-k heavy-hitter mask -------------------------
__global__ void topk_mask(float* __restrict__ maskout) {
    const int h = blockIdx.x;
    const int t = threadIdx.x;
    __shared__ float vals[SEL];
    __shared__ float rv[256];
    __shared__ int ri[256];

    for (int i = t; i < SEL; i += 256) vals[i] = g_colsum[h * S + i];
    float* m = maskout + (size_t)h * MASKW;
    for (int i = t; i < MASKW; i += 256) m[i] = (i >= MASKW - RECENT) ? 1.f : 0.f;
    __syncthreads();

    for (int it = 0; it < HEAVY; ++it) {
        float bv = -FLT_MAX; int bi = SEL;
        for (int i = t; i < SEL; i += 256) {
            float v = vals[i];
            if (v > bv) { bv = v; bi = i; }
        }
        rv[t] = bv; ri[t] = bi; __syncthreads();
        for (int off = 128; off; off >>= 1) {
            if (t < off) {
                if (rv[t + off] > rv[t] ||
                    (rv[t + off] == rv[t] && ri[t + off] < ri[t])) {
                    rv[t] = rv[t + off]; ri[t] = ri[t + off];
                }
            }
            __syncthreads();
        }
        if (t == 0) { m[ri[0]] = 1.f; vals[ri[0]] = -FLT_MAX; }
        __syncthreads();
    }
}

// ---------------------------------------------------------------------------
extern "C" void kernel_launch(void* const* d_in, const int* in_sizes, int n_in,
                              void* d_out, int out_size) {
    const float* hs      = (const float*)d_in[0];
    const float* amask   = (const float*)d_in[1];
    const int*   pos     = (const int*)  d_in[2];
    const float* qkv_w   = (const float*)d_in[3];
    const float* qkv_b   = (const float*)d_in[4];
    const float* dense_w = (const float*)d_in[5];
    const float* dense_b = (const float*)d_in[6];
    float* out = (float*)d_out;

    float *p_q, *p_k, *p_v, *p_ot;
    cudaGetSymbolAddress((void**)&p_q, g_q);
    cudaGetSymbolAddress((void**)&p_k, g_k);
    cudaGetSymbolAddress((void**)&p_v, g_v);
    cudaGetSymbolAddress((void**)&p_ot, g_ot);

    // 1) QKV: QK (FFMA pipe) + V (tensor pipe) in ONE launch -> pipe overlap
    fused_qkv<<<dim3(96, S / 128), 256>>>(hs, qkv_w, qkv_b, p_q, p_k, p_v, HID);
    // 2) RoPE in place
    rope_inplace<<<(NH * S * HALF + 255) / 256, 256>>>(pos);
    // 3-5) attention (exact fp32)
    scores_kernel<<<dim3(S / BN, S / BM, NH), 256>>>(amask);
    softmax_kernel<<<dim3(S, NH), 256>>>();
    pv_kernel<<<dim3(1, S / BM, NH), 256>>>();
    // 6+7) dense projection (tensor pipe) + colsum (LSU) in ONE launch
    fused_dense_colsum<<<dim3(32, 18), 256>>>(p_ot, dense_w, dense_b, out);
    // 8) top-k + mask
    topk_mask<<<NH, 256>>>(out + (size_t)S * HID);
}

// round 16
// speedup vs baseline: 1.0342x; 1.0342x over previous
#include <cuda_runtime.h>
#include <cuda_bf16.h>
#include <cfloat>
#include <math.h>
#include <cstdint>

#define S 2048
#define HID 4096
#define NH 32
#define D 128
#define QKV3 12288
#define ROT 32
#define HALF 16
#define HEAVY 204
#define RECENT 204
#define SEL (S - RECENT)       /* 1844 */
#define MASKW (S + 1)          /* 2049 */

#define BM 128
#define BN 128
#define BK 8
#define TM 8
#define TN 8
#define GBK 16
#define KP 132                 /* padded smem row stride for tf32 planes */

typedef unsigned long long ull;

// ------------------------- scratch (static device globals; no allocs) ------
__device__ float g_q[(size_t)NH * S * D];
__device__ float g_k[(size_t)NH * S * D];
__device__ float g_v[(size_t)NH * S * D];
__device__ float g_w[(size_t)NH * S * S];            // 536 MB
__device__ float g_ot[(size_t)S * HID];
__device__ float g_colsum[NH * S];

// ------------------------- packed f32x2 helpers ----------------------------
__device__ __forceinline__ ull pack_dup(float a) {
    ull d; asm("mov.b64 %0, {%1, %2};" : "=l"(d) : "f"(a), "f"(a)); return d;
}
__device__ __forceinline__ void ffma2(ull& c, ull a, ull b) {
    asm("fma.rn.f32x2 %0, %1, %2, %0;" : "+l"(c) : "l"(a), "l"(b));
}
__device__ __forceinline__ void unpack2(ull v, float& lo, float& hi) {
    asm("mov.b64 {%0, %1}, %2;" : "=f"(lo), "=f"(hi) : "l"(v));
}

// ------------------------- tf32 helpers ------------------------------------
__device__ __forceinline__ float to_tf32(float x) {
    float y;
    asm("cvt.rna.tf32.f32 %0, %1;" : "=f"(y) : "f"(x));
    return y;
}
__device__ __forceinline__ void mma_tf32(float c[4], const unsigned a[4], const unsigned b[2]) {
    asm volatile(
        "mma.sync.aligned.m16n8k8.row.col.f32.tf32.tf32.f32 "
        "{%0,%1,%2,%3}, {%4,%5,%6,%7}, {%8,%9}, {%0,%1,%2,%3};"
        : "+f"(c[0]), "+f"(c[1]), "+f"(c[2]), "+f"(c[3])
        : "r"(a[0]), "r"(a[1]), "r"(a[2]), "r"(a[3]), "r"(b[0]), "r"(b[1]));
}

// ---- single-tf32 MMA GEMM (double-buffered; round-13/14 math) -------------
// C = A[M,K] @ B[N,K]^T + bias.  Output-0 path only; measured rel 4.1e-4.
// mode 0: C[row][bx+col], ld = Nld.   mode 2: V tile x -> head x, writes
// vout[((h*S)+row)*128 + col]; weight/bias row base bx = (3x+2)*128.
__global__ void __launch_bounds__(256)
gemm_tf32_1x(const float* __restrict__ A,
             const float* __restrict__ B,
             const float* __restrict__ bias,
             float* __restrict__ Cdirect, float* __restrict__ vout,
             int Nld, int K, int mode) {
    __shared__ float Ah[2][16][KP];
    __shared__ float Bh[2][16][KP];
    const int bx = (mode == 2 ? (blockIdx.x * 3 + 2) : blockIdx.x) * 128;
    const int by = blockIdx.y * 128;
    const int t = threadIdx.x;
    const int lane = t & 31;
    const int warp = t >> 5;
    const int wr = (warp >> 2) * 64;
    const int wc = (warp & 3) * 32;
    const int g = lane >> 2;
    const int kq = lane & 3;

    const int lr = t & 127;
    const int lc = (t >> 7) * 8;

    const float* Ap = A + (size_t)(by + lr) * K + lc;
    const float* Bp = B + (size_t)(bx + lr) * K + lc;

    float4 a0, a1, b0, b1;
    a0 = *(const float4*)(Ap);     a1 = *(const float4*)(Ap + 4);
    b0 = *(const float4*)(Bp);     b1 = *(const float4*)(Bp + 4);

    {
        float a8[8], b8[8];
        *(float4*)&a8[0] = a0; *(float4*)&a8[4] = a1;
        *(float4*)&b8[0] = b0; *(float4*)&b8[4] = b1;
#pragma unroll
        for (int j = 0; j < 8; ++j) {
            Ah[0][lc + j][lr] = to_tf32(a8[j]);
            Bh[0][lc + j][lr] = to_tf32(b8[j]);
        }
    }
    __syncthreads();

    float acc[4][4][4] = {};
    const int nk = K / 16;

#pragma unroll 1
    for (int i = 0; i < nk; ++i) {
        const int cur = i & 1;
        if (i + 1 < nk) {
            const float* An = Ap + (size_t)(i + 1) * 16;
            const float* Bn = Bp + (size_t)(i + 1) * 16;
            a0 = *(const float4*)(An);     a1 = *(const float4*)(An + 4);
            b0 = *(const float4*)(Bn);     b1 = *(const float4*)(Bn + 4);
        }
#pragma unroll
        for (int ks = 0; ks < 2; ++ks) {
            const int kb = ks * 8;
            unsigned bf[4][2];
#pragma unroll
            for (int nt = 0; nt < 4; ++nt) {
                const int cn = wc + nt * 8 + g;
                bf[nt][0] = __float_as_uint(Bh[cur][kb + kq][cn]);
                bf[nt][1] = __float_as_uint(Bh[cur][kb + kq + 4][cn]);
            }
#pragma unroll
            for (int mt = 0; mt < 4; ++mt) {
                const int r = wr + mt * 16 + g;
                unsigned af[4];
                af[0] = __float_as_uint(Ah[cur][kb + kq][r]);
                af[1] = __float_as_uint(Ah[cur][kb + kq][r + 8]);
                af[2] = __float_as_uint(Ah[cur][kb + kq + 4][r]);
                af[3] = __float_as_uint(Ah[cur][kb + kq + 4][r + 8]);
#pragma unroll
                for (int nt = 0; nt < 4; ++nt)
                    mma_tf32(acc[mt][nt], af, bf[nt]);
            }
        }
        if (i + 1 < nk) {
            const int nxt = cur ^ 1;
            float a8[8], b8[8];
            *(float4*)&a8[0] = a0; *(float4*)&a8[4] = a1;
            *(float4*)&b8[0] = b0; *(float4*)&b8[4] = b1;
#pragma unroll
            for (int j = 0; j < 8; ++j) {
                Ah[nxt][lc + j][lr] = to_tf32(a8[j]);
                Bh[nxt][lc + j][lr] = to_tf32(b8[j]);
            }
        }
        __syncthreads();
    }

#pragma unroll
    for (int mt = 0; mt < 4; ++mt) {
        const int r = by + wr + mt * 16 + g;
#pragma unroll
        for (int nt = 0; nt < 4; ++nt) {
            const int cn = wc + nt * 8 + kq * 2;
            const float s0 = bias[bx + cn];
            const float s1 = bias[bx + cn + 1];
            if (mode == 0) {
                Cdirect[(size_t)r * Nld + bx + cn]           = acc[mt][nt][0] + s0;
                Cdirect[(size_t)r * Nld + bx + cn + 1]       = acc[mt][nt][1] + s1;
                Cdirect[(size_t)(r + 8) * Nld + bx + cn]     = acc[mt][nt][2] + s0;
                Cdirect[(size_t)(r + 8) * Nld + bx + cn + 1] = acc[mt][nt][3] + s1;
            } else {
                const int h = blockIdx.x;
                const size_t o0 = ((size_t)h * S + r) * D + cn;
                const size_t o1 = ((size_t)h * S + r + 8) * D + cn;
                vout[o0]     = acc[mt][nt][0] + s0;
                vout[o0 + 1] = acc[mt][nt][1] + s1;
                vout[o1]     = acc[mt][nt][2] + s0;
                vout[o1 + 1] = acc[mt][nt][3] + s1;
            }
        }
    }
}

// ---- QK part of QKV: exact fp32 FFMA2 GEMM into per-head q/k --------------
// grid (64, 16): x -> wtile = (x>>1)*3 + (x&1) (skips V tiles).
__global__ void __launch_bounds__(256, 2)
sgemm_qk_direct(const float* __restrict__ A,
                const float* __restrict__ B,
                const float* __restrict__ bias,
                float* __restrict__ q, float* __restrict__ k, int K) {
    __shared__ __align__(16) float As[2][GBK][128];
    __shared__ __align__(16) float Bs[2][GBK][128];
    const int wtile = (blockIdx.x >> 1) * 3 + (blockIdx.x & 1);
    const int bx = wtile * 128;
    const int by = blockIdx.y * 128;
    const int t = threadIdx.x;
    const int tr = t >> 4, tc = t & 15;
    const int lr = t & 127;
    const int lc = (t >> 7) * 8;

    const float* Ap = A + (size_t)(by + lr) * K + lc;
    const float* Bp = B + (size_t)(bx + lr) * K + lc;

    float4 a0, a1, b0, b1;
    a0 = *(const float4*)(Ap);     a1 = *(const float4*)(Ap + 4);
    b0 = *(const float4*)(Bp);     b1 = *(const float4*)(Bp + 4);

    ull acc2[TM][TN / 2];
#pragma unroll
    for (int i = 0; i < TM; ++i)
#pragma unroll
        for (int j = 0; j < TN / 2; ++j) acc2[i][j] = 0ULL;

    const int nk = K / GBK;
#pragma unroll 1
    for (int i = 0; i < nk; ++i) {
        const int cur = i & 1;
        As[cur][lc + 0][lr] = a0.x; As[cur][lc + 1][lr] = a0.y;
        As[cur][lc + 2][lr] = a0.z; As[cur][lc + 3][lr] = a0.w;
        As[cur][lc + 4][lr] = a1.x; As[cur][lc + 5][lr] = a1.y;
        As[cur][lc + 6][lr] = a1.z; As[cur][lc + 7][lr] = a1.w;
        Bs[cur][lc + 0][lr] = b0.x; Bs[cur][lc + 1][lr] = b0.y;
        Bs[cur][lc + 2][lr] = b0.z; Bs[cur][lc + 3][lr] = b0.w;
        Bs[cur][lc + 4][lr] = b1.x; Bs[cur][lc + 5][lr] = b1.y;
        Bs[cur][lc + 6][lr] = b1.z; Bs[cur][lc + 7][lr] = b1.w;
        __syncthreads();
        if (i + 1 < nk) {
            const float* An = Ap + (size_t)(i + 1) * GBK;
            const float* Bn = Bp + (size_t)(i + 1) * GBK;
            a0 = *(const float4*)(An);     a1 = *(const float4*)(An + 4);
            b0 = *(const float4*)(Bn);     b1 = *(const float4*)(Bn + 4);
        }
#pragma unroll
        for (int kk = 0; kk < GBK; ++kk) {
            float a[TM];
            *(float4*)&a[0] = *(const float4*)&As[cur][kk][tr * TM];
            *(float4*)&a[4] = *(const float4*)&As[cur][kk][tr * TM + 4];
            ulonglong2 q0 = *(const ulonglong2*)&Bs[cur][kk][tc * TN];
            ulonglong2 q1 = *(const ulonglong2*)&Bs[cur][kk][tc * TN + 4];
            ull b2[4] = { q0.x, q0.y, q1.x, q1.y };
            ull pa[TM];
#pragma unroll
            for (int x = 0; x < TM; ++x) pa[x] = pack_dup(a[x]);
#pragma unroll
            for (int x = 0; x < TM; ++x)
#pragma unroll
                for (int y = 0; y < TN / 2; ++y) ffma2(acc2[x][y], pa[x], b2[y]);
        }
        __syncthreads();
    }

    const int typ = wtile % 3;           // 0 = Q, 1 = K
    const int h = wtile / 3;
    float* outp = (typ == 0) ? q : k;
    const int cb = tc * TN;
    float bsv[TN];
#pragma unroll
    for (int j = 0; j < TN; ++j) bsv[j] = bias[bx + cb + j];
#pragma unroll
    for (int i = 0; i < TM; ++i) {
        float c[TN];
#pragma unroll
        for (int j = 0; j < TN / 2; ++j) unpack2(acc2[i][j], c[2 * j], c[2 * j + 1]);
        const int row = by + tr * TM + i;
        const size_t o = ((size_t)h * S + row) * D + cb;
        float4 v0, v1;
        v0.x = c[0] + bsv[0]; v0.y = c[1] + bsv[1];
        v0.z = c[2] + bsv[2]; v0.w = c[3] + bsv[3];
        v1.x = c[4] + bsv[4]; v1.y = c[5] + bsv[5];
        v1.z = c[6] + bsv[6]; v1.w = c[7] + bsv[7];
        *(float4*)&outp[o]     = v0;
        *(float4*)&outp[o + 4] = v1;
    }
}

// ------------------------- in-place RoPE on q/k rotary dims ----------------
__global__ void rope_inplace(const int* __restrict__ pos) {
    int idx = blockIdx.x * 256 + threadIdx.x;
    if (idx >= NH * S * HALF) return;
    const int i = idx & (HALF - 1);
    const int s = (idx >> 4) & (S - 1);
    const int h = idx >> 15;
    const float tpos = (float)pos[s];
    const float inv = powf(10000.0f, -(float)i * (1.0f / 16.0f));
    const float f = tpos * inv;
    const float c = cosf(f), sn = sinf(f);
    const size_t o = ((size_t)h * S + s) * D;

    float q1 = g_q[o + i], q2 = g_q[o + i + HALF];
    g_q[o + i]        = q1 * c + (-q2) * sn;
    g_q[o + i + HALF] = q2 * c + q1 * sn;

    float k1 = g_k[o + i], k2 = g_k[o + i + HALF];
    g_k[o + i]        = k1 * c + (-k2) * sn;
    g_k[o + i + HALF] = k2 * c + k1 * sn;
}

// ------ scores = QK^T / sqrt(D), causal (FFMA2, double-buffered) -----------
__global__ void scores_kernel(const float* __restrict__ amask) {
    const int h = blockIdx.z;
    const int bq = blockIdx.y * BM;
    const int bk = blockIdx.x * BN;
    if (bk > bq + BM - 1) return;
    const float* A = g_q + (size_t)h * S * D;
    const float* B = g_k + (size_t)h * S * D;
    float* C = g_w + (size_t)h * S * S;

    __shared__ __align__(16) float As[2][BK][BM];
    __shared__ __align__(16) float Bs[2][BK][BN];
    const int t = threadIdx.x;
    const int tr = t >> 4, tc = t & 15;
    const int lrow = t >> 1, lseg = (t & 1) * 4;
    ull acc2[TM][TN / 2];
#pragma unroll
    for (int i = 0; i < TM; ++i)
#pragma unroll
        for (int j = 0; j < TN / 2; ++j) acc2[i][j] = 0ULL;
    const float* Ab = A + (size_t)(bq + lrow) * D + lseg;
    const float* Bb = B + (size_t)(bk + lrow) * D + lseg;

    {
        float4 av = *(const float4*)(Ab);
        float4 bv = *(const float4*)(Bb);
        As[0][lseg + 0][lrow] = av.x; As[0][lseg + 1][lrow] = av.y;
        As[0][lseg + 2][lrow] = av.z; As[0][lseg + 3][lrow] = av.w;
        Bs[0][lseg + 0][lrow] = bv.x; Bs[0][lseg + 1][lrow] = bv.y;
        Bs[0][lseg + 2][lrow] = bv.z; Bs[0][lseg + 3][lrow] = bv.w;
    }
    __syncthreads();

    const int nit = D / BK;
#pragma unroll 1
    for (int it = 0; it < nit; ++it) {
        const int cur = it & 1;
        float4 av, bv;
        if (it + 1 < nit) {
            av = *(const float4*)(Ab + (it + 1) * BK);
            bv = *(const float4*)(Bb + (it + 1) * BK);
        }
#pragma unroll
        for (int kk = 0; kk < BK; ++kk) {
            float a[TM];
            *(float4*)&a[0] = *(const float4*)&As[cur][kk][tr * TM];
            *(float4*)&a[4] = *(const float4*)&As[cur][kk][tr * TM + 4];
            ulonglong2 q0 = *(const ulonglong2*)&Bs[cur][kk][tc * TN];
            ulonglong2 q1 = *(const ulonglong2*)&Bs[cur][kk][tc * TN + 4];
            ull b2[4] = { q0.x, q0.y, q1.x, q1.y };
            ull pa[TM];
#pragma unroll
            for (int x = 0; x < TM; ++x) pa[x] = pack_dup(a[x]);
#pragma unroll
            for (int x = 0; x < TM; ++x)
#pragma unroll
                for (int y = 0; y < TN / 2; ++y) ffma2(acc2[x][y], pa[x], b2[y]);
        }
        if (it + 1 < nit) {
            const int nxt = cur ^ 1;
            As[nxt][lseg + 0][lrow] = av.x; As[nxt][lseg + 1][lrow] = av.y;
            As[nxt][lseg + 2][lrow] = av.z; As[nxt][lseg + 3][lrow] = av.w;
            Bs[nxt][lseg + 0][lrow] = bv.x; Bs[nxt][lseg + 1][lrow] = bv.y;
            Bs[nxt][lseg + 2][lrow] = bv.z; Bs[nxt][lseg + 3][lrow] = bv.w;
        }
        __syncthreads();
    }
    const float scale = 0.08838834764831845f;
#pragma unroll
    for (int i = 0; i < TM; ++i) {
        float c[TN];
#pragma unroll
        for (int j = 0; j < TN / 2; ++j) unpack2(acc2[i][j], c[2 * j], c[2 * j + 1]);
        const int q = bq + tr * TM + i;
#pragma unroll
        for (int j = 0; j < TN; ++j) {
            const int k = bk + tc * TN + j;
            if (k <= q) C[(size_t)q * S + k] = c[j] * scale + amask[k];
        }
    }
}

// ------------- row softmax (zero-fills only within diagonal block) ---------
// pv only ever reads zeros inside q's own 128-block (its k-loop stops at the
// block edge), so filling to the edge is sufficient. Validated in round 15.
__global__ void softmax_kernel() {
    const int q = blockIdx.x, h = blockIdx.y;
    float* row = g_w + (size_t)h * S * S + (size_t)q * S;
    __shared__ float buf[S];
    __shared__ float red[256];
    const int t = threadIdx.x;
    const int n = q + 1;
    const int edge = ((q >> 7) + 1) << 7;   // end of q's 128-diagonal block

    float m = -FLT_MAX;
    for (int i = t; i < n; i += 256) { float v = row[i]; buf[i] = v; m = fmaxf(m, v); }
    red[t] = m; __syncthreads();
    for (int off = 128; off; off >>= 1) {
        if (t < off) red[t] = fmaxf(red[t], red[t + off]);
        __syncthreads();
    }
    m = red[0]; __syncthreads();

    float sum = 0.f;
    for (int i = t; i < n; i += 256) { float e = expf(buf[i] - m); buf[i] = e; sum += e; }
    red[t] = sum; __syncthreads();
    for (int off = 128; off; off >>= 1) {
        if (t < off) red[t] += red[t + off];
        __syncthreads();
    }
    const float inv = 1.0f / red[0];

    for (int i = t; i < n; i += 256) row[i] = buf[i] * inv;
    for (int i = n + t; i < edge; i += 256) row[i] = 0.f;
}

// ------ O = W @ V (causal-bounded K loop, FFMA2, double-buffered) ----------
__global__ void pv_kernel() {
    const int h = blockIdx.z;
    const int bq = blockIdx.y * BM;
    const float* A = g_w + (size_t)h * S * S;
    const float* B = g_v + (size_t)h * S * D;

    __shared__ __align__(16) float As[2][BK][BM];
    __shared__ __align__(16) float Bs[2][BK][BN];
    const int t = threadIdx.x;
    const int tr = t >> 4, tc = t & 15;
    const int lrow = t >> 1, lseg = (t & 1) * 4;
    ull acc2[TM][TN / 2];
#pragma unroll
    for (int i = 0; i < TM; ++i)
#pragma unroll
        for (int j = 0; j < TN / 2; ++j) acc2[i][j] = 0ULL;
    const int kmax = bq + BM;
    const int nit = kmax / BK;

    {
        float4 av = *(const float4*)(A + (size_t)(bq + lrow) * S + lseg);
        float4 bv = *(const float4*)(B + (size_t)(t >> 5) * D + (t & 31) * 4);
        As[0][lseg + 0][lrow] = av.x; As[0][lseg + 1][lrow] = av.y;
        As[0][lseg + 2][lrow] = av.z; As[0][lseg + 3][lrow] = av.w;
        *(float4*)&Bs[0][t >> 5][(t & 31) * 4] = bv;
    }
    __syncthreads();

#pragma unroll 1
    for (int it = 0; it < nit; ++it) {
        const int cur = it & 1;
        float4 av, bv;
        if (it + 1 < nit) {
            const int k0 = (it + 1) * BK;
            av = *(const float4*)(A + (size_t)(bq + lrow) * S + k0 + lseg);
            bv = *(const float4*)(B + (size_t)(k0 + (t >> 5)) * D + (t & 31) * 4);
        }
#pragma unroll
        for (int kk = 0; kk < BK; ++kk) {
            float a[TM];
            *(float4*)&a[0] = *(const float4*)&As[cur][kk][tr * TM];
            *(float4*)&a[4] = *(const float4*)&As[cur][kk][tr * TM + 4];
            ulonglong2 q0 = *(const ulonglong2*)&Bs[cur][kk][tc * TN];
            ulonglong2 q1 = *(const ulonglong2*)&Bs[cur][kk][tc * TN + 4];
            ull b2[4] = { q0.x, q0.y, q1.x, q1.y };
            ull pa[TM];
#pragma unroll
            for (int x = 0; x < TM; ++x) pa[x] = pack_dup(a[x]);
#pragma unroll
            for (int x = 0; x < TM; ++x)
#pragma unroll
                for (int y = 0; y < TN / 2; ++y) ffma2(acc2[x][y], pa[x], b2[y]);
        }
        if (it + 1 < nit) {
            const int nxt = cur ^ 1;
            As[nxt][lseg + 0][lrow] = av.x; As[nxt][lseg + 1][lrow] = av.y;
            As[nxt][lseg + 2][lrow] = av.z; As[nxt][lseg + 3][lrow] = av.w;
            *(float4*)&Bs[nxt][t >> 5][(t & 31) * 4] = bv;
        }
        __syncthreads();
    }
#pragma unroll
    for (int i = 0; i < TM; ++i) {
        float c[TN];
#pragma unroll
        for (int j = 0; j < TN / 2; ++j) unpack2(acc2[i][j], c[2 * j], c[2 * j + 1]);
        const size_t row = bq + tr * TM + i;
        *(float4*)&g_ot[row * HID + h * D + tc * TN]     = *(float4*)&c[0];
        *(float4*)&g_ot[row * HID + h * D + tc * TN + 4] = *(float4*)&c[4];
    }
}

// ------------- column sums of weights (exactly causal: q from k) -----------
// Entries with q < k are never read (true zeros in the reference sum), so
// starting at q = k is exact. Validated in round 15.
__global__ void colsum_kernel() {
    const int h = blockIdx.y;
    const int k0 = blockIdx.x * 256;
    const int k = k0 + threadIdx.x;
    const float* base = g_w + (size_t)h * S * S;
    float s = 0.f;
#pragma unroll 4
    for (int q = k; q < S; ++q) s += base[(size_t)q * S + k];
    g_colsum[h * S + k] = s;
}

// ------------------------- top-k heavy-hitter mask -------------------------
__global__ void topk_mask(float* __restrict__ maskout) {
    const int h = blockIdx.x;
    const int t = threadIdx.x;
    __shared__ float vals[SEL];
    __shared__ float rv[256];
    __shared__ int ri[256];

    for (int i = t; i < SEL; i += 256) vals[i] = g_colsum[h * S + i];
    float* m = maskout + (size_t)h * MASKW;
    for (int i = t; i < MASKW; i += 256) m[i] = (i >= MASKW - RECENT) ? 1.f : 0.f;
    __syncthreads();

    for (int it = 0; it < HEAVY; ++it) {
        float bv = -FLT_MAX; int bi = SEL;
        for (int i = t; i < SEL; i += 256) {
            float v = vals[i];
            if (v > bv) { bv = v; bi = i; }
        }
        rv[t] = bv; ri[t] = bi; __syncthreads();
        for (int off = 128; off; off >>= 1) {
            if (t < off) {
                if (rv[t + off] > rv[t] ||
                    (rv[t + off] == rv[t] && ri[t + off] < ri[t])) {
                    rv[t] = rv[t + off]; ri[t] = ri[t + off];
                }
            }
            __syncthreads();
        }
        if (t == 0) { m[ri[0]] = 1.f; vals[ri[0]] = -FLT_MAX; }
        __syncthreads();
    }
}

// ---------------------------------------------------------------------------
extern "C" void kernel_launch(void* const* d_in, const int* in_sizes, int n_in,
                              void* d_out, int out_size) {
    const float* hs      = (const float*)d_in[0];
    const float* amask   = (const float*)d_in[1];
    const int*   pos     = (const int*)  d_in[2];
    const float* qkv_w   = (const float*)d_in[3];
    const float* qkv_b   = (const float*)d_in[4];
    const float* dense_w = (const float*)d_in[5];
    const float* dense_b = (const float*)d_in[6];
    float* out = (float*)d_out;

    float *p_q, *p_k, *p_v, *p_ot;
    cudaGetSymbolAddress((void**)&p_q, g_q);
    cudaGetSymbolAddress((void**)&p_k, g_k);
    cudaGetSymbolAddress((void**)&p_v, g_v);
    cudaGetSymbolAddress((void**)&p_ot, g_ot);

    // 1a) QK part of QKV: exact fp32 FFMA2 (output-1 path, bit-identical)
    sgemm_qk_direct<<<dim3(64, S / 128), 256>>>(hs, qkv_w, qkv_b, p_q, p_k, HID);
    // 1b) V part of QKV: single-tf32 MMA (output-0 only)
    gemm_tf32_1x<<<dim3(32, S / 128), 256>>>(hs, qkv_w, qkv_b, nullptr, p_v, 0, HID, 2);
    // 2) RoPE in place
    rope_inplace<<<(NH * S * HALF + 255) / 256, 256>>>(pos);
    // 3-5) attention (exact fp32)
    scores_kernel<<<dim3(S / BN, S / BM, NH), 256>>>(amask);
    softmax_kernel<<<dim3(S, NH), 256>>>();
    pv_kernel<<<dim3(1, S / BM, NH), 256>>>();
    // 6) colsum for the mask (causal)
    colsum_kernel<<<dim3(S / 256, NH), 256>>>();
    // 7) dense projection: single-tf32 MMA straight into d_out
    gemm_tf32_1x<<<dim3(HID / 128, S / 128), 256>>>(p_ot, dense_w, dense_b, out, nullptr, HID, HID, 0);
    // 8) top-k + mask
    topk_mask<<<NH, 256>>>(out + (size_t)S * HID);
}

// round 17
// speedup vs baseline: 1.0464x; 1.0117x over previous
#include <cuda_runtime.h>
#include <cuda_bf16.h>
#include <cfloat>
#include <math.h>
#include <cstdint>

#define S 2048
#define HID 4096
#define NH 32
#define D 128
#define QKV3 12288
#define ROT 32
#define HALF 16
#define HEAVY 204
#define RECENT 204
#define SEL (S - RECENT)       /* 1844 */
#define MASKW (S + 1)          /* 2049 */

#define BM 128
#define BN 128
#define BK 8
#define TM 8
#define TN 8
#define GBK 16
#define KP 132                 /* padded smem row stride for tf32 planes */

typedef unsigned long long ull;

// ------------------------- scratch (static device globals; no allocs) ------
__device__ float g_q[(size_t)NH * S * D];
__device__ float g_k[(size_t)NH * S * D];
__device__ float g_v[(size_t)NH * S * D];
__device__ float g_w[(size_t)NH * S * S];            // 536 MB
__device__ float g_ot[(size_t)S * HID];
__device__ float g_colsum[NH * S];

// ------------------------- packed f32x2 helpers ----------------------------
__device__ __forceinline__ ull pack_dup(float a) {
    ull d; asm("mov.b64 %0, {%1, %2};" : "=l"(d) : "f"(a), "f"(a)); return d;
}
__device__ __forceinline__ void ffma2(ull& c, ull a, ull b) {
    asm("fma.rn.f32x2 %0, %1, %2, %0;" : "+l"(c) : "l"(a), "l"(b));
}
__device__ __forceinline__ void unpack2(ull v, float& lo, float& hi) {
    asm("mov.b64 {%0, %1}, %2;" : "=f"(lo), "=f"(hi) : "l"(v));
}

// ------------------------- tf32 helpers ------------------------------------
__device__ __forceinline__ float to_tf32(float x) {
    float y;
    asm("cvt.rna.tf32.f32 %0, %1;" : "=f"(y) : "f"(x));
    return y;
}
__device__ __forceinline__ void mma_tf32(float c[4], const unsigned a[4], const unsigned b[2]) {
    asm volatile(
        "mma.sync.aligned.m16n8k8.row.col.f32.tf32.tf32.f32 "
        "{%0,%1,%2,%3}, {%4,%5,%6,%7}, {%8,%9}, {%0,%1,%2,%3};"
        : "+f"(c[0]), "+f"(c[1]), "+f"(c[2]), "+f"(c[3])
        : "r"(a[0]), "r"(a[1]), "r"(a[2]), "r"(a[3]), "r"(b[0]), "r"(b[1]));
}

// ---- single-tf32 MMA GEMM (double-buffered, af-preloaded bursts) ----------
// C = A[M,K] @ B[N,K]^T + bias.  Output-0 path only; measured rel 4.1e-4.
// All 16 A-fragments for a k8-step are loaded BEFORE the 16-MMA burst so the
// HMMA pipe sees a long independent issue window instead of 4-MMA groups
// gated by LDS latency. Each accumulator's MMA chain is unchanged (one MMA
// per ks in identical order) -> bit-identical to rounds 13/14/16.
// mode 0: C[row][bx+col], ld = Nld.   mode 2: V tile x -> head x, writes
// vout[((h*S)+row)*128 + col]; weight/bias row base bx = (3x+2)*128.
__global__ void __launch_bounds__(256, 2)
gemm_tf32_1x(const float* __restrict__ A,
             const float* __restrict__ B,
             const float* __restrict__ bias,
             float* __restrict__ Cdirect, float* __restrict__ vout,
             int Nld, int K, int mode) {
    __shared__ float Ah[2][16][KP];
    __shared__ float Bh[2][16][KP];
    const int bx = (mode == 2 ? (blockIdx.x * 3 + 2) : blockIdx.x) * 128;
    const int by = blockIdx.y * 128;
    const int t = threadIdx.x;
    const int lane = t & 31;
    const int warp = t >> 5;
    const int wr = (warp >> 2) * 64;
    const int wc = (warp & 3) * 32;
    const int g = lane >> 2;
    const int kq = lane & 3;

    const int lr = t & 127;
    const int lc = (t >> 7) * 8;

    const float* Ap = A + (size_t)(by + lr) * K + lc;
    const float* Bp = B + (size_t)(bx + lr) * K + lc;

    float4 a0, a1, b0, b1;
    a0 = *(const float4*)(Ap);     a1 = *(const float4*)(Ap + 4);
    b0 = *(const float4*)(Bp);     b1 = *(const float4*)(Bp + 4);

    {
        float a8[8], b8[8];
        *(float4*)&a8[0] = a0; *(float4*)&a8[4] = a1;
        *(float4*)&b8[0] = b0; *(float4*)&b8[4] = b1;
#pragma unroll
        for (int j = 0; j < 8; ++j) {
            Ah[0][lc + j][lr] = to_tf32(a8[j]);
            Bh[0][lc + j][lr] = to_tf32(b8[j]);
        }
    }
    __syncthreads();

    float acc[4][4][4] = {};
    const int nk = K / 16;

#pragma unroll 1
    for (int i = 0; i < nk; ++i) {
        const int cur = i & 1;
        if (i + 1 < nk) {
            const float* An = Ap + (size_t)(i + 1) * 16;
            const float* Bn = Bp + (size_t)(i + 1) * 16;
            a0 = *(const float4*)(An);     a1 = *(const float4*)(An + 4);
            b0 = *(const float4*)(Bn);     b1 = *(const float4*)(Bn + 4);
        }
#pragma unroll
        for (int ks = 0; ks < 2; ++ks) {
            const int kb = ks * 8;
            unsigned bf[4][2];
            unsigned af[4][4];
#pragma unroll
            for (int nt = 0; nt < 4; ++nt) {
                const int cn = wc + nt * 8 + g;
                bf[nt][0] = __float_as_uint(Bh[cur][kb + kq][cn]);
                bf[nt][1] = __float_as_uint(Bh[cur][kb + kq + 4][cn]);
            }
#pragma unroll
            for (int mt = 0; mt < 4; ++mt) {
                const int r = wr + mt * 16 + g;
                af[mt][0] = __float_as_uint(Ah[cur][kb + kq][r]);
                af[mt][1] = __float_as_uint(Ah[cur][kb + kq][r + 8]);
                af[mt][2] = __float_as_uint(Ah[cur][kb + kq + 4][r]);
                af[mt][3] = __float_as_uint(Ah[cur][kb + kq + 4][r + 8]);
            }
            // 16 independent MMAs back-to-back (same per-acc order as before)
#pragma unroll
            for (int mt = 0; mt < 4; ++mt)
#pragma unroll
                for (int nt = 0; nt < 4; ++nt)
                    mma_tf32(acc[mt][nt], af[mt], bf[nt]);
        }
        if (i + 1 < nk) {
            const int nxt = cur ^ 1;
            float a8[8], b8[8];
            *(float4*)&a8[0] = a0; *(float4*)&a8[4] = a1;
            *(float4*)&b8[0] = b0; *(float4*)&b8[4] = b1;
#pragma unroll
            for (int j = 0; j < 8; ++j) {
                Ah[nxt][lc + j][lr] = to_tf32(a8[j]);
                Bh[nxt][lc + j][lr] = to_tf32(b8[j]);
            }
        }
        __syncthreads();
    }

#pragma unroll
    for (int mt = 0; mt < 4; ++mt) {
        const int r = by + wr + mt * 16 + g;
#pragma unroll
        for (int nt = 0; nt < 4; ++nt) {
            const int cn = wc + nt * 8 + kq * 2;
            const float s0 = bias[bx + cn];
            const float s1 = bias[bx + cn + 1];
            if (mode == 0) {
                Cdirect[(size_t)r * Nld + bx + cn]           = acc[mt][nt][0] + s0;
                Cdirect[(size_t)r * Nld + bx + cn + 1]       = acc[mt][nt][1] + s1;
                Cdirect[(size_t)(r + 8) * Nld + bx + cn]     = acc[mt][nt][2] + s0;
                Cdirect[(size_t)(r + 8) * Nld + bx + cn + 1] = acc[mt][nt][3] + s1;
            } else {
                const int h = blockIdx.x;
                const size_t o0 = ((size_t)h * S + r) * D + cn;
                const size_t o1 = ((size_t)h * S + r + 8) * D + cn;
                vout[o0]     = acc[mt][nt][0] + s0;
                vout[o0 + 1] = acc[mt][nt][1] + s1;
                vout[o1]     = acc[mt][nt][2] + s0;
                vout[o1 + 1] = acc[mt][nt][3] + s1;
            }
        }
    }
}

// ---- QK part of QKV: exact fp32 FFMA2 GEMM into per-head q/k --------------
// grid (64, 16): x -> wtile = (x>>1)*3 + (x&1) (skips V tiles).
__global__ void __launch_bounds__(256, 2)
sgemm_qk_direct(const float* __restrict__ A,
                const float* __restrict__ B,
                const float* __restrict__ bias,
                float* __restrict__ q, float* __restrict__ k, int K) {
    __shared__ __align__(16) float As[2][GBK][128];
    __shared__ __align__(16) float Bs[2][GBK][128];
    const int wtile = (blockIdx.x >> 1) * 3 + (blockIdx.x & 1);
    const int bx = wtile * 128;
    const int by = blockIdx.y * 128;
    const int t = threadIdx.x;
    const int tr = t >> 4, tc = t & 15;
    const int lr = t & 127;
    const int lc = (t >> 7) * 8;

    const float* Ap = A + (size_t)(by + lr) * K + lc;
    const float* Bp = B + (size_t)(bx + lr) * K + lc;

    float4 a0, a1, b0, b1;
    a0 = *(const float4*)(Ap);     a1 = *(const float4*)(Ap + 4);
    b0 = *(const float4*)(Bp);     b1 = *(const float4*)(Bp + 4);

    ull acc2[TM][TN / 2];
#pragma unroll
    for (int i = 0; i < TM; ++i)
#pragma unroll
        for (int j = 0; j < TN / 2; ++j) acc2[i][j] = 0ULL;

    const int nk = K / GBK;
#pragma unroll 1
    for (int i = 0; i < nk; ++i) {
        const int cur = i & 1;
        As[cur][lc + 0][lr] = a0.x; As[cur][lc + 1][lr] = a0.y;
        As[cur][lc + 2][lr] = a0.z; As[cur][lc + 3][lr] = a0.w;
        As[cur][lc + 4][lr] = a1.x; As[cur][lc + 5][lr] = a1.y;
        As[cur][lc + 6][lr] = a1.z; As[cur][lc + 7][lr] = a1.w;
        Bs[cur][lc + 0][lr] = b0.x; Bs[cur][lc + 1][lr] = b0.y;
        Bs[cur][lc + 2][lr] = b0.z; Bs[cur][lc + 3][lr] = b0.w;
        Bs[cur][lc + 4][lr] = b1.x; Bs[cur][lc + 5][lr] = b1.y;
        Bs[cur][lc + 6][lr] = b1.z; Bs[cur][lc + 7][lr] = b1.w;
        __syncthreads();
        if (i + 1 < nk) {
            const float* An = Ap + (size_t)(i + 1) * GBK;
            const float* Bn = Bp + (size_t)(i + 1) * GBK;
            a0 = *(const float4*)(An);     a1 = *(const float4*)(An + 4);
            b0 = *(const float4*)(Bn);     b1 = *(const float4*)(Bn + 4);
        }
#pragma unroll
        for (int kk = 0; kk < GBK; ++kk) {
            float a[TM];
            *(float4*)&a[0] = *(const float4*)&As[cur][kk][tr * TM];
            *(float4*)&a[4] = *(const float4*)&As[cur][kk][tr * TM + 4];
            ulonglong2 q0 = *(const ulonglong2*)&Bs[cur][kk][tc * TN];
            ulonglong2 q1 = *(const ulonglong2*)&Bs[cur][kk][tc * TN + 4];
            ull b2[4] = { q0.x, q0.y, q1.x, q1.y };
            ull pa[TM];
#pragma unroll
            for (int x = 0; x < TM; ++x) pa[x] = pack_dup(a[x]);
#pragma unroll
            for (int x = 0; x < TM; ++x)
#pragma unroll
                for (int y = 0; y < TN / 2; ++y) ffma2(acc2[x][y], pa[x], b2[y]);
        }
        __syncthreads();
    }

    const int typ = wtile % 3;           // 0 = Q, 1 = K
    const int h = wtile / 3;
    float* outp = (typ == 0) ? q : k;
    const int cb = tc * TN;
    float bsv[TN];
#pragma unroll
    for (int j = 0; j < TN; ++j) bsv[j] = bias[bx + cb + j];
#pragma unroll
    for (int i = 0; i < TM; ++i) {
        float c[TN];
#pragma unroll
        for (int j = 0; j < TN / 2; ++j) unpack2(acc2[i][j], c[2 * j], c[2 * j + 1]);
        const int row = by + tr * TM + i;
        const size_t o = ((size_t)h * S + row) * D + cb;
        float4 v0, v1;
        v0.x = c[0] + bsv[0]; v0.y = c[1] + bsv[1];
        v0.z = c[2] + bsv[2]; v0.w = c[3] + bsv[3];
        v1.x = c[4] + bsv[4]; v1.y = c[5] + bsv[5];
        v1.z = c[6] + bsv[6]; v1.w = c[7] + bsv[7];
        *(float4*)&outp[o]     = v0;
        *(float4*)&outp[o + 4] = v1;
    }
}

// ------------------------- in-place RoPE on q/k rotary dims ----------------
__global__ void rope_inplace(const int* __restrict__ pos) {
    int idx = blockIdx.x * 256 + threadIdx.x;
    if (idx >= NH * S * HALF) return;
    const int i = idx & (HALF - 1);
    const int s = (idx >> 4) & (S - 1);
    const int h = idx >> 15;
    const float tpos = (float)pos[s];
    const float inv = powf(10000.0f, -(float)i * (1.0f / 16.0f));
    const float f = tpos * inv;
    const float c = cosf(f), sn = sinf(f);
    const size_t o = ((size_t)h * S + s) * D;

    float q1 = g_q[o + i], q2 = g_q[o + i + HALF];
    g_q[o + i]        = q1 * c + (-q2) * sn;
    g_q[o + i + HALF] = q2 * c + q1 * sn;

    float k1 = g_k[o + i], k2 = g_k[o + i + HALF];
    g_k[o + i]        = k1 * c + (-k2) * sn;
    g_k[o + i + HALF] = k2 * c + k1 * sn;
}

// ------ scores = QK^T / sqrt(D), causal (FFMA2, double-buffered) -----------
__global__ void scores_kernel(const float* __restrict__ amask) {
    const int h = blockIdx.z;
    const int bq = blockIdx.y * BM;
    const int bk = blockIdx.x * BN;
    if (bk > bq + BM - 1) return;
    const float* A = g_q + (size_t)h * S * D;
    const float* B = g_k + (size_t)h * S * D;
    float* C = g_w + (size_t)h * S * S;

    __shared__ __align__(16) float As[2][BK][BM];
    __shared__ __align__(16) float Bs[2][BK][BN];
    const int t = threadIdx.x;
    const int tr = t >> 4, tc = t & 15;
    const int lrow = t >> 1, lseg = (t & 1) * 4;
    ull acc2[TM][TN / 2];
#pragma unroll
    for (int i = 0; i < TM; ++i)
#pragma unroll
        for (int j = 0; j < TN / 2; ++j) acc2[i][j] = 0ULL;
    const float* Ab = A + (size_t)(bq + lrow) * D + lseg;
    const float* Bb = B + (size_t)(bk + lrow) * D + lseg;

    {
        float4 av = *(const float4*)(Ab);
        float4 bv = *(const float4*)(Bb);
        As[0][lseg + 0][lrow] = av.x; As[0][lseg + 1][lrow] = av.y;
        As[0][lseg + 2][lrow] = av.z; As[0][lseg + 3][lrow] = av.w;
        Bs[0][lseg + 0][lrow] = bv.x; Bs[0][lseg + 1][lrow] = bv.y;
        Bs[0][lseg + 2][lrow] = bv.z; Bs[0][lseg + 3][lrow] = bv.w;
    }
    __syncthreads();

    const int nit = D / BK;
#pragma unroll 1
    for (int it = 0; it < nit; ++it) {
        const int cur = it & 1;
        float4 av, bv;
        if (it + 1 < nit) {
            av = *(const float4*)(Ab + (it + 1) * BK);
            bv = *(const float4*)(Bb + (it + 1) * BK);
        }
#pragma unroll
        for (int kk = 0; kk < BK; ++kk) {
            float a[TM];
            *(float4*)&a[0] = *(const float4*)&As[cur][kk][tr * TM];
            *(float4*)&a[4] = *(const float4*)&As[cur][kk][tr * TM + 4];
            ulonglong2 q0 = *(const ulonglong2*)&Bs[cur][kk][tc * TN];
            ulonglong2 q1 = *(const ulonglong2*)&Bs[cur][kk][tc * TN + 4];
            ull b2[4] = { q0.x, q0.y, q1.x, q1.y };
            ull pa[TM];
#pragma unroll
            for (int x = 0; x < TM; ++x) pa[x] = pack_dup(a[x]);
#pragma unroll
            for (int x = 0; x < TM; ++x)
#pragma unroll
                for (int y = 0; y < TN / 2; ++y) ffma2(acc2[x][y], pa[x], b2[y]);
        }
        if (it + 1 < nit) {
            const int nxt = cur ^ 1;
            As[nxt][lseg + 0][lrow] = av.x; As[nxt][lseg + 1][lrow] = av.y;
            As[nxt][lseg + 2][lrow] = av.z; As[nxt][lseg + 3][lrow] = av.w;
            Bs[nxt][lseg + 0][lrow] = bv.x; Bs[nxt][lseg + 1][lrow] = bv.y;
            Bs[nxt][lseg + 2][lrow] = bv.z; Bs[nxt][lseg + 3][lrow] = bv.w;
        }
        __syncthreads();
    }
    const float scale = 0.08838834764831845f;
#pragma unroll
    for (int i = 0; i < TM; ++i) {
        float c[TN];
#pragma unroll
        for (int j = 0; j < TN / 2; ++j) unpack2(acc2[i][j], c[2 * j], c[2 * j + 1]);
        const int q = bq + tr * TM + i;
#pragma unroll
        for (int j = 0; j < TN; ++j) {
            const int k = bk + tc * TN + j;
            if (k <= q) C[(size_t)q * S + k] = c[j] * scale + amask[k];
        }
    }
}

// ------------- row softmax (zero-fills only within diagonal block) ---------
__global__ void softmax_kernel() {
    const int q = blockIdx.x, h = blockIdx.y;
    float* row = g_w + (size_t)h * S * S + (size_t)q * S;
    __shared__ float buf[S];
    __shared__ float red[256];
    const int t = threadIdx.x;
    const int n = q + 1;
    const int edge = ((q >> 7) + 1) << 7;   // end of q's 128-diagonal block

    float m = -FLT_MAX;
    for (int i = t; i < n; i += 256) { float v = row[i]; buf[i] = v; m = fmaxf(m, v); }
    red[t] = m; __syncthreads();
    for (int off = 128; off; off >>= 1) {
        if (t < off) red[t] = fmaxf(red[t], red[t + off]);
        __syncthreads();
    }
    m = red[0]; __syncthreads();

    float sum = 0.f;
    for (int i = t; i < n; i += 256) { float e = expf(buf[i] - m); buf[i] = e; sum += e; }
    red[t] = sum; __syncthreads();
    for (int off = 128; off; off >>= 1) {
        if (t < off) red[t] += red[t + off];
        __syncthreads();
    }
    const float inv = 1.0f / red[0];

    for (int i = t; i < n; i += 256) row[i] = buf[i] * inv;
    for (int i = n + t; i < edge; i += 256) row[i] = 0.f;
}

// ------ O = W @ V (causal-bounded K loop, FFMA2, double-buffered) ----------
__global__ void pv_kernel() {
    const int h = blockIdx.z;
    const int bq = blockIdx.y * BM;
    const float* A = g_w + (size_t)h * S * S;
    const float* B = g_v + (size_t)h * S * D;

    __shared__ __align__(16) float As[2][BK][BM];
    __shared__ __align__(16) float Bs[2][BK][BN];
    const int t = threadIdx.x;
    const int tr = t >> 4, tc = t & 15;
    const int lrow = t >> 1, lseg = (t & 1) * 4;
    ull acc2[TM][TN / 2];
#pragma unroll
    for (int i = 0; i < TM; ++i)
#pragma unroll
        for (int j = 0; j < TN / 2; ++j) acc2[i][j] = 0ULL;
    const int kmax = bq + BM;
    const int nit = kmax / BK;

    {
        float4 av = *(const float4*)(A + (size_t)(bq + lrow) * S + lseg);
        float4 bv = *(const float4*)(B + (size_t)(t >> 5) * D + (t & 31) * 4);
        As[0][lseg + 0][lrow] = av.x; As[0][lseg + 1][lrow] = av.y;
        As[0][lseg + 2][lrow] = av.z; As[0][lseg + 3][lrow] = av.w;
        *(float4*)&Bs[0][t >> 5][(t & 31) * 4] = bv;
    }
    __syncthreads();

#pragma unroll 1
    for (int it = 0; it < nit; ++it) {
        const int cur = it & 1;
        float4 av, bv;
        if (it + 1 < nit) {
            const int k0 = (it + 1) * BK;
            av = *(const float4*)(A + (size_t)(bq + lrow) * S + k0 + lseg);
            bv = *(const float4*)(B + (size_t)(k0 + (t >> 5)) * D + (t & 31) * 4);
        }
#pragma unroll
        for (int kk = 0; kk < BK; ++kk) {
            float a[TM];
            *(float4*)&a[0] = *(const float4*)&As[cur][kk][tr * TM];
            *(float4*)&a[4] = *(const float4*)&As[cur][kk][tr * TM + 4];
            ulonglong2 q0 = *(const ulonglong2*)&Bs[cur][kk][tc * TN];
            ulonglong2 q1 = *(const ulonglong2*)&Bs[cur][kk][tc * TN + 4];
            ull b2[4] = { q0.x, q0.y, q1.x, q1.y };
            ull pa[TM];
#pragma unroll
            for (int x = 0; x < TM; ++x) pa[x] = pack_dup(a[x]);
#pragma unroll
            for (int x = 0; x < TM; ++x)
#pragma unroll
                for (int y = 0; y < TN / 2; ++y) ffma2(acc2[x][y], pa[x], b2[y]);
        }
        if (it + 1 < nit) {
            const int nxt = cur ^ 1;
            As[nxt][lseg + 0][lrow] = av.x; As[nxt][lseg + 1][lrow] = av.y;
            As[nxt][lseg + 2][lrow] = av.z; As[nxt][lseg + 3][lrow] = av.w;
            *(float4*)&Bs[nxt][t >> 5][(t & 31) * 4] = bv;
        }
        __syncthreads();
    }
#pragma unroll
    for (int i = 0; i < TM; ++i) {
        float c[TN];
#pragma unroll
        for (int j = 0; j < TN / 2; ++j) unpack2(acc2[i][j], c[2 * j], c[2 * j + 1]);
        const size_t row = bq + tr * TM + i;
        *(float4*)&g_ot[row * HID + h * D + tc * TN]     = *(float4*)&c[0];
        *(float4*)&g_ot[row * HID + h * D + tc * TN + 4] = *(float4*)&c[4];
    }
}

// ------------- column sums of weights (exactly causal: q from k) -----------
__global__ void colsum_kernel() {
    const int h = blockIdx.y;
    const int k0 = blockIdx.x * 256;
    const int k = k0 + threadIdx.x;
    const float* base = g_w + (size_t)h * S * S;
    float s = 0.f;
#pragma unroll 4
    for (int q = k; q < S; ++q) s += base[(size_t)q * S + k];
    g_colsum[h * S + k] = s;
}

// ------------------------- top-k heavy-hitter mask -------------------------
__global__ void topk_mask(float* __restrict__ maskout) {
    const int h = blockIdx.x;
    const int t = threadIdx.x;
    __shared__ float vals[SEL];
    __shared__ float rv[256];
    __shared__ int ri[256];

    for (int i = t; i < SEL; i += 256) vals[i] = g_colsum[h * S + i];
    float* m = maskout + (size_t)h * MASKW;
    for (int i = t; i < MASKW; i += 256) m[i] = (i >= MASKW - RECENT) ? 1.f : 0.f;
    __syncthreads();

    for (int it = 0; it < HEAVY; ++it) {
        float bv = -FLT_MAX; int bi = SEL;
        for (int i = t; i < SEL; i += 256) {
            float v = vals[i];
            if (v > bv) { bv = v; bi = i; }
        }
        rv[t] = bv; ri[t] = bi; __syncthreads();
        for (int off = 128; off; off >>= 1) {
            if (t < off) {
                if (rv[t + off] > rv[t] ||
                    (rv[t + off] == rv[t] && ri[t + off] < ri[t])) {
                    rv[t] = rv[t + off]; ri[t] = ri[t + off];
                }
            }
            __syncthreads();
        }
        if (t == 0) { m[ri[0]] = 1.f; vals[ri[0]] = -FLT_MAX; }
        __syncthreads();
    }
}

// ---------------------------------------------------------------------------
extern "C" void kernel_launch(void* const* d_in, const int* in_sizes, int n_in,
                              void* d_out, int out_size) {
    const float* hs      = (const float*)d_in[0];
    const float* amask   = (const float*)d_in[1];
    const int*   pos     = (const int*)  d_in[2];
    const float* qkv_w   = (const float*)d_in[3];
    const float* qkv_b   = (const float*)d_in[4];
    const float* dense_w = (const float*)d_in[5];
    const float* dense_b = (const float*)d_in[6];
    float* out = (float*)d_out;

    float *p_q, *p_k, *p_v, *p_ot;
    cudaGetSymbolAddress((void**)&p_q, g_q);
    cudaGetSymbolAddress((void**)&p_k, g_k);
    cudaGetSymbolAddress((void**)&p_v, g_v);
    cudaGetSymbolAddress((void**)&p_ot, g_ot);

    // 1a) QK part of QKV: exact fp32 FFMA2 (output-1 path, bit-identical)
    sgemm_qk_direct<<<dim3(64, S / 128), 256>>>(hs, qkv_w, qkv_b, p_q, p_k, HID);
    // 1b) V part of QKV: single-tf32 MMA, af-preloaded bursts (output-0 only)
    gemm_tf32_1x<<<dim3(32, S / 128), 256>>>(hs, qkv_w, qkv_b, nullptr, p_v, 0, HID, 2);
    // 2) RoPE in place
    rope_inplace<<<(NH * S * HALF + 255) / 256, 256>>>(pos);
    // 3-5) attention (exact fp32)
    scores_kernel<<<dim3(S / BN, S / BM, NH), 256>>>(amask);
    softmax_kernel<<<dim3(S, NH), 256>>>();
    pv_kernel<<<dim3(1, S / BM, NH), 256>>>();
    // 6) colsum for the mask (causal)
    colsum_kernel<<<dim3(S / 256, NH), 256>>>();
    // 7) dense projection: single-tf32 MMA, af-preloaded bursts, into d_out
    gemm_tf32_1x<<<dim3(HID / 128, S / 128), 256>>>(p_ot, dense_w, dense_b, out, nullptr, HID, HID, 0);
    // 8) top-k + mask
    topk_mask<<<NH, 256>>>(out + (size_t)S * HID);
}